// round 2
// baseline (speedup 1.0000x reference)
#include <cuda_runtime.h>
#include <math.h>

#define NN 100000
#define NE 3200000
#define HID 16

// Scratch (static device globals — no runtime allocation allowed)
__device__ float d_dinv[NN];
__device__ float d_g  [NN * HID];   // dinv-scaled features (pre-aggregation)
__device__ float d_agg[NN * HID];   // edge-aggregated messages
__device__ float d_h  [NN * HID];   // layer activation

// ---------------- degree / normalization ----------------
__global__ void k_init_deg() {
    int i = blockIdx.x * blockDim.x + threadIdx.x;
    if (i < NN) d_dinv[i] = 1.0f;   // self-loop weight
}

__global__ void k_deg_acc(const int* __restrict__ col,
                          const float* __restrict__ ew) {
    int e = blockIdx.x * blockDim.x + threadIdx.x;
    if (e < NE) atomicAdd(&d_dinv[col[e]], ew[e]);
}

__global__ void k_dinv() {
    int i = blockIdx.x * blockDim.x + threadIdx.x;
    if (i < NN) {
        float v = d_dinv[i];
        d_dinv[i] = (v > 0.0f) ? rsqrtf(v) : 0.0f;
    }
}

// ---------------- layer 1 GEMM: g = dinv * (x @ W1) ----------------
// 256 threads = 16 nodes/block x 16 channels. W1 (128x16) staged in smem.
__global__ void k_gemm1(const float* __restrict__ x,
                        const float* __restrict__ W1) {
    __shared__ float Ws[128 * HID];
    int t = threadIdx.x;
    for (int j = t; j < 128 * HID; j += 256) Ws[j] = W1[j];
    __syncthreads();

    int node = blockIdx.x * 16 + (t >> 4);
    int c    = t & 15;
    if (node >= NN) return;

    const float* xr = x + (long long)node * 128;
    float acc = 0.0f;
#pragma unroll
    for (int k = 0; k < 128; k++)
        acc += __ldg(xr + k) * Ws[k * HID + c];

    d_g[node * HID + c] = d_dinv[node] * acc;
}

// ---------------- layer 2 GEMM: g = dinv * (h @ W2) ----------------
__global__ void k_gemm2(const float* __restrict__ W2) {
    __shared__ float Ws[HID * HID];
    int t = threadIdx.x;
    if (t < HID * HID) Ws[t] = W2[t];
    __syncthreads();

    int node = blockIdx.x * 16 + (t >> 4);
    int c    = t & 15;
    if (node >= NN) return;

    const float* hr = d_h + node * HID;
    float acc = 0.0f;
#pragma unroll
    for (int k = 0; k < HID; k++)
        acc += hr[k] * Ws[k * HID + c];

    d_g[node * HID + c] = d_dinv[node] * acc;
}

// ---------------- zero the aggregation buffer ----------------
__global__ void k_zero_agg() {
    int i = blockIdx.x * blockDim.x + threadIdx.x;
    if (i < NN * HID) d_agg[i] = 0.0f;
}

// ---------------- edge scatter: agg[col] += ew * g[row] ----------------
// 16 threads per edge (one per channel): coalesced 64B gather, index loads
// broadcast within each 16-lane group.
__global__ void k_edges(const int* __restrict__ row,
                        const int* __restrict__ col,
                        const float* __restrict__ ew) {
    int idx = blockIdx.x * 256 + threadIdx.x;
    int e = idx >> 4;
    int c = idx & 15;
    if (e < NE) {
        int r = row[e];
        int d = col[e];
        float w = ew[e];
        atomicAdd(&d_agg[d * HID + c], w * d_g[r * HID + c]);
    }
}

// ---------------- combine: h = relu(dinv*(agg + g) + b) ----------------
__global__ void k_combine(const float* __restrict__ b) {
    int idx = blockIdx.x * blockDim.x + threadIdx.x;
    if (idx < NN * HID) {
        int i = idx >> 4;
        int c = idx & 15;
        float v = d_dinv[i] * (d_agg[idx] + d_g[idx]) + b[c];
        d_h[idx] = fmaxf(v, 0.0f);
    }
}

// ---------------- final: out = relu(dinv*(agg+g)+b2) @ Wout + bout ----
__global__ void k_out(const float* __restrict__ b2,
                      const float* __restrict__ Wout,
                      const float* __restrict__ bout,
                      float* __restrict__ out) {
    int i = blockIdx.x * blockDim.x + threadIdx.x;
    if (i >= NN) return;
    float dv = d_dinv[i];
    float s = 0.0f;
#pragma unroll
    for (int c = 0; c < HID; c++) {
        float v = fmaxf(dv * (d_agg[i * HID + c] + d_g[i * HID + c]) + __ldg(b2 + c), 0.0f);
        s += v * __ldg(Wout + c);
    }
    out[i] = s + __ldg(bout);
}

extern "C" void kernel_launch(void* const* d_in, const int* in_sizes, int n_in,
                              void* d_out, int out_size) {
    const float* x    = (const float*)d_in[0];
    const int*   ei   = (const int*)d_in[1];   // [2, NE] int32 (JAX x64 disabled)
    const float* ea   = (const float*)d_in[2];
    // d_in[3]=y, d_in[4]=batch (unused)
    const float* W1   = (const float*)d_in[5];
    const float* b1   = (const float*)d_in[6];
    const float* W2   = (const float*)d_in[7];
    const float* b2   = (const float*)d_in[8];
    const float* Wout = (const float*)d_in[9];
    const float* bout = (const float*)d_in[10];
    float*       out  = (float*)d_out;

    const int* row = ei;
    const int* col = ei + NE;

    const int T = 256;
    int gN   = (NN + T - 1) / T;          // node-wise
    int gE   = (NE + T - 1) / T;          // edge-wise
    int gNC  = (NN * HID + T - 1) / T;    // node*channel
    int gG   = (NN + 15) / 16;            // gemm blocks (16 nodes each)
    int gEC  = (NE * 16 + T - 1) / T;     // edge*channel (51.2M threads)

    // normalization
    k_init_deg<<<gN, T>>>();
    k_deg_acc<<<gE, T>>>(col, ea);
    k_dinv<<<gN, T>>>();

    // layer 1
    k_gemm1<<<gG, T>>>(x, W1);
    k_zero_agg<<<gNC, T>>>();
    k_edges<<<gEC, T>>>(row, col, ea);
    k_combine<<<gNC, T>>>(b1);

    // layer 2
    k_gemm2<<<gG, T>>>(W2);
    k_zero_agg<<<gNC, T>>>();
    k_edges<<<gEC, T>>>(row, col, ea);

    // fused combine + output projection
    k_out<<<gN, T>>>(b2, Wout, bout, out);
}

// round 3
// speedup vs baseline: 2.1392x; 2.1392x over previous
#include <cuda_runtime.h>
#include <math.h>

#define NN 100000
#define NE 3200000
#define HID 16

// Scratch (static device globals — no runtime allocation allowed)
__device__ float d_dinv[NN];
__device__ float d_g  [NN * HID];   // dinv-scaled features (pre-aggregation)
__device__ float d_agg[NN * HID];   // edge-aggregated messages

// ---------------- degree / normalization ----------------
__global__ void k_init_deg() {
    int i = blockIdx.x * blockDim.x + threadIdx.x;
    if (i < NN) d_dinv[i] = 1.0f;   // self-loop weight
}

__global__ void k_deg_acc(const int* __restrict__ col,
                          const float* __restrict__ ew) {
    int e = blockIdx.x * blockDim.x + threadIdx.x;
    if (e < NE) atomicAdd(&d_dinv[col[e]], ew[e]);
}

__global__ void k_dinv() {
    int i = blockIdx.x * blockDim.x + threadIdx.x;
    if (i < NN) {
        float v = d_dinv[i];
        d_dinv[i] = (v > 0.0f) ? rsqrtf(v) : 0.0f;
    }
}

// ---------------- layer 1 GEMM: g = dinv * (x @ W1); also zero agg -------
// 256 threads = 16 nodes x 16 channels. x tile staged in smem via coalesced
// float4 loads; compute phase reads are broadcast-only (conflict-free).
__global__ void k_gemm1(const float* __restrict__ x,
                        const float* __restrict__ W1) {
    __shared__ float xs[16 * 128];     // 8 KB
    __shared__ float Ws[128 * HID];    // 8 KB
    int t = threadIdx.x;
    int base = blockIdx.x * 16;
    int nvalid = NN - base; if (nvalid > 16) nvalid = 16;

    // coalesced stage of x rows (float4)
    const float4* xg = (const float4*)x + (size_t)base * 32;
    float4* xs4 = (float4*)xs;
    int n4 = nvalid * 32;
    for (int j = t; j < n4; j += 256) xs4[j] = xg[j];
    for (int j = t; j < 128 * HID; j += 256) Ws[j] = W1[j];
    __syncthreads();

    int nloc = t >> 4;
    int node = base + nloc;
    int c    = t & 15;
    if (node >= NN) return;

    float acc = 0.0f;
    const float4* xrow = (const float4*)xs + nloc * 32;
#pragma unroll
    for (int kk = 0; kk < 32; kk++) {
        float4 xv = xrow[kk];                 // LDS.128, broadcast
        int kb = kk * 4;
        acc += xv.x * Ws[(kb + 0) * HID + c];
        acc += xv.y * Ws[(kb + 1) * HID + c];
        acc += xv.z * Ws[(kb + 2) * HID + c];
        acc += xv.w * Ws[(kb + 3) * HID + c];
    }
    int idx = node * HID + c;
    d_g[idx]   = d_dinv[node] * acc;
    d_agg[idx] = 0.0f;                         // zero for edge pass 1
}

// ---------------- edge scatter: agg[col] += ew * g[row] ----------------
// 4 threads per edge: one float4 gather + one vector red.global (RED.128).
__global__ void k_edges(const int* __restrict__ row,
                        const int* __restrict__ col,
                        const float* __restrict__ ew) {
    int idx = blockIdx.x * 256 + threadIdx.x;
    int e  = idx >> 2;
    int cq = idx & 3;
    if (e >= NE) return;
    int r   = __ldg(row + e);
    int d   = __ldg(col + e);
    float w = __ldg(ew  + e);
    float4 g = __ldg((const float4*)d_g + r * 4 + cq);
    float* p = d_agg + d * HID + cq * 4;       // 16B aligned
    asm volatile("red.global.add.v4.f32 [%0], {%1,%2,%3,%4};"
                 :: "l"(p), "f"(w * g.x), "f"(w * g.y),
                    "f"(w * g.z), "f"(w * g.w)
                 : "memory");
}

// ------- fused: h = relu(dinv*(agg+g)+b1);  g = dinv*(h @ W2); zero agg --
__global__ void k_combine_gemm2(const float* __restrict__ b1,
                                const float* __restrict__ W2) {
    __shared__ float hs[16 * HID];
    __shared__ float W2s[HID * HID];
    int t = threadIdx.x;
    if (t < HID * HID) W2s[t] = W2[t];

    int nloc = t >> 4;
    int node = blockIdx.x * 16 + nloc;
    int c    = t & 15;
    bool ok  = (node < NN);
    float dv = 0.0f;
    int idx  = 0;
    if (ok) {
        idx = node * HID + c;
        dv  = d_dinv[node];
        float v = dv * (d_agg[idx] + d_g[idx]) + b1[c];
        hs[t] = fmaxf(v, 0.0f);
    }
    __syncthreads();
    if (!ok) return;

    float acc = 0.0f;
#pragma unroll
    for (int k = 0; k < HID; k++)
        acc += hs[nloc * HID + k] * W2s[k * HID + c];

    d_g[idx]   = dv * acc;
    d_agg[idx] = 0.0f;                          // zero for edge pass 2
}

// ---------------- final: out = relu(dinv*(agg+g)+b2) @ Wout + bout ------
__global__ void k_out(const float* __restrict__ b2,
                      const float* __restrict__ Wout,
                      const float* __restrict__ bout,
                      float* __restrict__ out) {
    int i = blockIdx.x * blockDim.x + threadIdx.x;
    if (i >= NN) return;
    float dv = d_dinv[i];
    const float4* a4 = (const float4*)d_agg + i * 4;
    const float4* g4 = (const float4*)d_g   + i * 4;
    float s = 0.0f;
#pragma unroll
    for (int q = 0; q < 4; q++) {
        float4 a = a4[q], g = g4[q];
        int c = q * 4;
        s += fmaxf(dv * (a.x + g.x) + __ldg(b2 + c + 0), 0.0f) * __ldg(Wout + c + 0);
        s += fmaxf(dv * (a.y + g.y) + __ldg(b2 + c + 1), 0.0f) * __ldg(Wout + c + 1);
        s += fmaxf(dv * (a.z + g.z) + __ldg(b2 + c + 2), 0.0f) * __ldg(Wout + c + 2);
        s += fmaxf(dv * (a.w + g.w) + __ldg(b2 + c + 3), 0.0f) * __ldg(Wout + c + 3);
    }
    out[i] = s + __ldg(bout);
}

extern "C" void kernel_launch(void* const* d_in, const int* in_sizes, int n_in,
                              void* d_out, int out_size) {
    const float* x    = (const float*)d_in[0];
    const int*   ei   = (const int*)d_in[1];   // [2, NE] int32
    const float* ea   = (const float*)d_in[2];
    // d_in[3]=y, d_in[4]=batch (unused)
    const float* W1   = (const float*)d_in[5];
    const float* b1   = (const float*)d_in[6];
    const float* W2   = (const float*)d_in[7];
    const float* b2   = (const float*)d_in[8];
    const float* Wout = (const float*)d_in[9];
    const float* bout = (const float*)d_in[10];
    float*       out  = (float*)d_out;

    const int* row = ei;
    const int* col = ei + NE;

    const int T = 256;
    int gN  = (NN + T - 1) / T;            // node-wise
    int gE  = (NE + T - 1) / T;            // edge-wise (deg)
    int gG  = (NN + 15) / 16;              // 16 nodes/block
    int gE4 = (NE * 4 + T - 1) / T;        // 4 threads/edge

    // normalization
    k_init_deg<<<gN, T>>>();
    k_deg_acc<<<gE, T>>>(col, ea);
    k_dinv<<<gN, T>>>();

    // layer 1
    k_gemm1<<<gG, T>>>(x, W1);             // also zeroes agg
    k_edges<<<gE4, T>>>(row, col, ea);
    k_combine_gemm2<<<gG, T>>>(b1, W2);    // also zeroes agg

    // layer 2
    k_edges<<<gE4, T>>>(row, col, ea);

    // fused combine + output projection
    k_out<<<gN, T>>>(b2, Wout, bout, out);
}